// round 17
// baseline (speedup 1.0000x reference)
#include <cuda_runtime.h>

#define BB 16
#define NN 4096
#define DD 768
#define MM 8
#define BN (BB*NN)
#define NCHUNK 64
#define NC (NN/NCHUNK)   // 64
#define LN_EPS 1e-3f
// 1/sqrt(768)
#define SIM_SCALE 0.03608439182435161f

// ---------------- device scratch (no allocations allowed) ----------------
__device__ float g_qg[MM*DD];          // q*gamma
__device__ float g_qgsum[MM];          // sum_d q*gamma
__device__ float g_qb[MM];             // sum_d q*beta
__device__ float g_sim[BB*MM*NN];      // logits, overwritten in-place with w = attn*rstd
__device__ float g_mu[BN];
__device__ float g_rstd[BN];
__device__ float g_c[BB*MM];           // sum_n w*mu
__device__ float g_part[BB*NCHUNK*MM*DD]; // partial weighted sums (25MB)

// ---------------- f32x2 packed-math helpers ----------------
union F4U2 { float4 f; unsigned long long u[2]; };

__device__ __forceinline__ void ffma2(unsigned long long& d,
                                      unsigned long long a,
                                      unsigned long long b) {
    asm("fma.rn.f32x2 %0, %1, %2, %0;" : "+l"(d) : "l"(a), "l"(b));
}
__device__ __forceinline__ void fadd2(unsigned long long& d,
                                      unsigned long long a) {
    asm("add.rn.f32x2 %0, %1, %0;" : "+l"(d) : "l"(a));
}
__device__ __forceinline__ unsigned long long fpack2(float lo, float hi) {
    unsigned long long r;
    asm("mov.b64 %0, {%1, %2};" : "=l"(r) : "f"(lo), "f"(hi));
    return r;
}
__device__ __forceinline__ float2 funpack2(unsigned long long v) {
    float2 r;
    asm("mov.b64 {%0, %1}, %2;" : "=f"(r.x), "=f"(r.y) : "l"(v));
    return r;
}

__device__ __forceinline__ float warp_allreduce_sum(float v) {
#pragma unroll
    for (int o = 16; o > 0; o >>= 1) v += __shfl_xor_sync(0xffffffffu, v, o);
    return v;
}

// ---------------- K0: precompute qg, qgsum, qb ----------------
__global__ void k0_prep(const float* __restrict__ q,
                        const float* __restrict__ gamma,
                        const float* __restrict__ beta) {
    int m = blockIdx.x;
    int t = threadIdx.x;
    float s1 = 0.f, s2 = 0.f;
    for (int d = t; d < DD; d += 256) {
        float qq = q[m * DD + d];
        float qg = qq * gamma[d];
        g_qg[m * DD + d] = qg;
        s1 += qg;
        s2 += qq * beta[d];
    }
    __shared__ float r1[256], r2[256];
    r1[t] = s1; r2[t] = s2;
    __syncthreads();
    for (int s = 128; s > 0; s >>= 1) {
        if (t < s) { r1[t] += r1[t + s]; r2[t] += r2[t + s]; }
        __syncthreads();
    }
    if (t == 0) { g_qgsum[m] = r1[0]; g_qb[m] = r2[0]; }
}

// ---------------- K1: LayerNorm stats + 8 query dots per row (f32x2) ----------------
// One warp handles 2 rows (amortizes qg smem traffic). CTA = 8 warps = 16 rows.
__global__ __launch_bounds__(256) void k1_ln_logits(const float* __restrict__ x) {
    __shared__ float4 qg_s[MM * DD / 4];  // 1536 float4 = 24KB
    int t = threadIdx.x;
    const float4* qg4 = (const float4*)g_qg;
    for (int i = t; i < MM * DD / 4; i += 256) qg_s[i] = qg4[i];
    __syncthreads();

    int warp = t >> 5, lane = t & 31;
    int r0 = blockIdx.x * 16 + warp * 2;   // even row; r0 and r0+1 same batch
    const float4* x4 = (const float4*)x;

    F4U2 xa[6], xb[6];
#pragma unroll
    for (int k = 0; k < 6; k++) xa[k].f = x4[(size_t)r0 * 192 + lane + 32 * k];
#pragma unroll
    for (int k = 0; k < 6; k++) xb[k].f = x4[(size_t)(r0 + 1) * 192 + lane + 32 * k];

    unsigned long long s1a = 0ull, s2a = 0ull, s1b = 0ull, s2b = 0ull;
#pragma unroll
    for (int k = 0; k < 6; k++) {
        fadd2(s1a, xa[k].u[0]); fadd2(s1a, xa[k].u[1]);
        ffma2(s2a, xa[k].u[0], xa[k].u[0]); ffma2(s2a, xa[k].u[1], xa[k].u[1]);
        fadd2(s1b, xb[k].u[0]); fadd2(s1b, xb[k].u[1]);
        ffma2(s2b, xb[k].u[0], xb[k].u[0]); ffma2(s2b, xb[k].u[1], xb[k].u[1]);
    }

    unsigned long long da2[MM], db2[MM];
#pragma unroll
    for (int m = 0; m < MM; m++) {
        da2[m] = 0ull; db2[m] = 0ull;
#pragma unroll
        for (int k = 0; k < 6; k++) {
            F4U2 qv; qv.f = qg_s[m * 192 + lane + 32 * k];
            ffma2(da2[m], qv.u[0], xa[k].u[0]);
            ffma2(da2[m], qv.u[1], xa[k].u[1]);
            ffma2(db2[m], qv.u[0], xb[k].u[0]);
            ffma2(db2[m], qv.u[1], xb[k].u[1]);
        }
    }

    float2 p;
    p = funpack2(s1a); float s1af = p.x + p.y;
    p = funpack2(s2a); float s2af = p.x + p.y;
    p = funpack2(s1b); float s1bf = p.x + p.y;
    p = funpack2(s2b); float s2bf = p.x + p.y;
    float da[MM], db[MM];
#pragma unroll
    for (int m = 0; m < MM; m++) {
        p = funpack2(da2[m]); da[m] = p.x + p.y;
        p = funpack2(db2[m]); db[m] = p.x + p.y;
    }

    // butterfly all-reduce (every lane gets full sums)
    s1af = warp_allreduce_sum(s1af);
    s2af = warp_allreduce_sum(s2af);
    s1bf = warp_allreduce_sum(s1bf);
    s2bf = warp_allreduce_sum(s2bf);
#pragma unroll
    for (int m = 0; m < MM; m++) {
        da[m] = warp_allreduce_sum(da[m]);
        db[m] = warp_allreduce_sum(db[m]);
    }

    const float invD = 1.f / (float)DD;
    float mua = s1af * invD, mub = s1bf * invD;
    float ra = rsqrtf(s2af * invD - mua * mua + LN_EPS);
    float rb = rsqrtf(s2bf * invD - mub * mub + LN_EPS);

    if (lane == 0) {
        g_mu[r0] = mua;   g_rstd[r0] = ra;
        g_mu[r0 + 1] = mub; g_rstd[r0 + 1] = rb;
    }

    int b0 = r0 >> 12;        // r0 / 4096
    int n0 = r0 & (NN - 1);   // r0 % 4096

    float qs = 0.f, qbv = 0.f;
    if (lane < MM) { qs = g_qgsum[lane]; qbv = g_qb[lane]; }

#pragma unroll
    for (int m = 0; m < MM; m++) {
        if (lane == m) {
            size_t base = ((size_t)(b0 * MM + m)) * NN + n0;
            g_sim[base]     = SIM_SCALE * (ra * (da[m] - mua * qs) + qbv);
            g_sim[base + 1] = SIM_SCALE * (rb * (db[m] - mub * qs) + qbv);
        }
    }
}

// ---------------- K2: softmax over N, fold in rstd, compute c ----------------
__global__ __launch_bounds__(256) void k2_softmax() {
    int bm = blockIdx.x;          // b*MM + m
    int b = bm >> 3;
    int t = threadIdx.x;
    float* row = g_sim + (size_t)bm * NN;

    float v[16];
    float mx = -1e30f;
#pragma unroll
    for (int i = 0; i < 16; i++) {
        v[i] = row[t + 256 * i];
        mx = fmaxf(mx, v[i]);
    }

    __shared__ float sred[256];
    sred[t] = mx; __syncthreads();
    for (int s = 128; s > 0; s >>= 1) {
        if (t < s) sred[t] = fmaxf(sred[t], sred[t + s]);
        __syncthreads();
    }
    mx = sred[0]; __syncthreads();

    float sum = 0.f;
#pragma unroll
    for (int i = 0; i < 16; i++) {
        v[i] = __expf(v[i] - mx);
        sum += v[i];
    }
    sred[t] = sum; __syncthreads();
    for (int s = 128; s > 0; s >>= 1) {
        if (t < s) sred[t] += sred[t + s];
        __syncthreads();
    }
    float inv = 1.f / sred[0]; __syncthreads();

    float cacc = 0.f;
#pragma unroll
    for (int i = 0; i < 16; i++) {
        int n = t + 256 * i;
        float w = v[i] * inv * g_rstd[b * NN + n];
        row[n] = w;                      // in-place: sim -> w
        cacc += w * g_mu[b * NN + n];
    }
    sred[t] = cacc; __syncthreads();
    for (int s = 128; s > 0; s >>= 1) {
        if (t < s) sred[t] += sred[t + s];
        __syncthreads();
    }
    if (t == 0) g_c[bm] = sred[0];
}

// ---------------- K3: partial weighted sums (float4 loads + f32x2 FMA) ----------------
// CTA handles (batch, N-chunk of NC=64 rows), full D. 192 threads, thread t owns
// float4 column t (d = 4t..4t+3). Weights pre-packed {w,w} in smem → LDS.64 broadcast.
__global__ __launch_bounds__(192) void k3_wsum(const float* __restrict__ x) {
    int b  = blockIdx.x / NCHUNK;
    int ch = blockIdx.x % NCHUNK;
    int t = threadIdx.x;
    int n0 = ch * NC;

    __shared__ unsigned long long ws2[MM * NC];   // 4KB, {w,w} packed
    for (int i = t; i < MM * NC; i += 192) {
        int m = i / NC, n = i % NC;
        float w = g_sim[((size_t)(b * MM + m)) * NN + n0 + n];
        ws2[i] = fpack2(w, w);
    }
    __syncthreads();

    unsigned long long a0[MM], a1[MM];
#pragma unroll
    for (int m = 0; m < MM; m++) { a0[m] = 0ull; a1[m] = 0ull; }

    const float4* xb4 = (const float4*)x + ((size_t)(b * NN + n0)) * 192;
#pragma unroll 4
    for (int n = 0; n < NC; n++) {
        F4U2 xv; xv.f = xb4[(size_t)n * 192 + t];
#pragma unroll
        for (int m = 0; m < MM; m++) {
            unsigned long long w = ws2[m * NC + n];
            ffma2(a0[m], w, xv.u[0]);
            ffma2(a1[m], w, xv.u[1]);
        }
    }

    float4* p4 = (float4*)(g_part + ((size_t)(b * NCHUNK + ch)) * MM * DD);
#pragma unroll
    for (int m = 0; m < MM; m++) {
        float2 lo = funpack2(a0[m]);
        float2 hi = funpack2(a1[m]);
        float4 o; o.x = lo.x; o.y = lo.y; o.z = hi.x; o.w = hi.y;
        p4[m * 192 + t] = o;
    }
}

// ---------------- K4: reduce partials, apply gamma/beta and -c ----------------
__global__ __launch_bounds__(192) void k4_final(const float* __restrict__ gamma,
                                                const float* __restrict__ beta,
                                                float* __restrict__ out) {
    int bm = blockIdx.x;
    int b = bm >> 3, m = bm & 7;
    int t = threadIdx.x;
    float c = g_c[bm];

    const float4* p4 = (const float4*)g_part;
    float4 s = make_float4(0.f, 0.f, 0.f, 0.f);
#pragma unroll 8
    for (int ch = 0; ch < NCHUNK; ch++) {
        float4 v = p4[((size_t)(b * NCHUNK + ch) * MM + m) * 192 + t];
        s.x += v.x; s.y += v.y; s.z += v.z; s.w += v.w;
    }
    float4 g = ((const float4*)gamma)[t];
    float4 be = ((const float4*)beta)[t];
    float4 o;
    o.x = g.x * (s.x - c) + be.x;
    o.y = g.y * (s.y - c) + be.y;
    o.z = g.z * (s.z - c) + be.z;
    o.w = g.w * (s.w - c) + be.w;
    ((float4*)out)[(size_t)bm * 192 + t] = o;
}

extern "C" void kernel_launch(void* const* d_in, const int* in_sizes, int n_in,
                              void* d_out, int out_size) {
    const float* x     = (const float*)d_in[0];
    const float* q     = (const float*)d_in[1];
    const float* gamma = (const float*)d_in[2];
    const float* beta  = (const float*)d_in[3];
    float* out = (float*)d_out;

    k0_prep<<<MM, 256>>>(q, gamma, beta);
    k1_ln_logits<<<BN / 16, 256>>>(x);
    k2_softmax<<<BB * MM, 256>>>();
    k3_wsum<<<BB * NCHUNK, 192>>>(x);
    k4_final<<<BB * MM, 192>>>(gamma, beta, out);
}